// round 12
// baseline (speedup 1.0000x reference)
#include <cuda_runtime.h>
#include <cuda_bf16.h>
#include <cstdint>

// Problem dims
#define NB 8
#define DD 32
#define NC 32
#define NO 32
// positions = 262144

typedef unsigned long long ull;

// ---------------- scratch ----------------
__device__ float g_m1[NB*DD*DD*NC];
__device__ float g_m2[NB*DD*DD*NC];
__device__ float g_m3[NB*DD*DD*NC];
__device__ float g_pij[NB*DD*NO];
__device__ float g_pik[NB*DD*NO];
__device__ float g_pjk[NB*DD*NO];
__device__ float g_pall[NB*NO];
__device__ float g_PA[NB*DD*DD*NO];
__device__ float g_PB[NB*DD*DD*NO];
__device__ float g_PC[NB*DD*DD*NO];
// pre-split W (bf16 hi/lo pairs, packed 2-per-u32): [group 0..3][o:32][c2:16]
// groups 1..3 pre-scaled by 1/32
__device__ uint32_t g_Wh4[4*512];
__device__ uint32_t g_Wl4[4*512];

// ---------------- helpers ----------------
// fp32 pair -> (hi, lo) bf16x2
__device__ __forceinline__ void split_pair(float a, float b, uint32_t& hi, uint32_t& lo) {
    __nv_bfloat162 h = __floats2bfloat162_rn(a, b);
    float2 hf = __bfloat1622float2(h);
    __nv_bfloat162 l = __floats2bfloat162_rn(a - hf.x, b - hf.y);
    hi = *(uint32_t*)&h;
    lo = *(uint32_t*)&l;
}

#define MMA16816(d, a, b) \
    asm volatile("mma.sync.aligned.m16n8k16.row.col.f32.bf16.bf16.f32 " \
                 "{%0,%1,%2,%3}, {%4,%5,%6,%7}, {%8,%9}, {%0,%1,%2,%3};" \
                 : "+f"(d[0]), "+f"(d[1]), "+f"(d[2]), "+f"(d[3]) \
                 : "r"(a[0]), "r"(a[1]), "r"(a[2]), "r"(a[3]), "r"(b[0]), "r"(b[1]))

// ---------------- K1: axis sums (grid 768) ----------------
__global__ __launch_bounds__(256) void k_means(const float* __restrict__ x) {
    int sel = blockIdx.x >> 8;
    int blk = blockIdx.x & 255;
    int b = blk >> 5, d = blk & 31;
    int t = threadIdx.x;
    const float4* x4 = (const float4*)x;

    if (sel == 0) {
        float4 acc = make_float4(0.f, 0.f, 0.f, 0.f);
        #pragma unroll 8
        for (int i = 0; i < DD; i++) {
            float4 v = x4[((b * DD + i) * DD + d) * 256 + t];
            acc.x += v.x; acc.y += v.y; acc.z += v.z; acc.w += v.w;
        }
        ((float4*)g_m1)[(b * DD + d) * 256 + t] = acc;
    } else if (sel == 1) {
        float4 acc = make_float4(0.f, 0.f, 0.f, 0.f);
        #pragma unroll 8
        for (int j = 0; j < DD; j++) {
            float4 v = x4[((b * DD + d) * DD + j) * 256 + t];
            acc.x += v.x; acc.y += v.y; acc.z += v.z; acc.w += v.w;
        }
        ((float4*)g_m2)[(b * DD + d) * 256 + t] = acc;
    } else {
        int j = t >> 3, c4 = t & 7;
        float4 acc = make_float4(0.f, 0.f, 0.f, 0.f);
        #pragma unroll 8
        for (int k = 0; k < DD; k++) {
            float4 v = x4[((b * DD + d) * DD + j) * 256 + k * 8 + c4];
            acc.x += v.x; acc.y += v.y; acc.z += v.z; acc.w += v.w;
        }
        ((float4*)g_m3)[(b * DD + d) * 256 + j * 8 + c4] = acc;
    }
}

// ---------------- K2: pools + small projections + W split (grid 777) ----------------
__global__ __launch_bounds__(128) void k_small(const float* __restrict__ W,
                                               const float* __restrict__ bias) {
    int gid = blockIdx.x;
    int t = threadIdx.x;

    if (gid == 776) {
        #pragma unroll
        for (int idx = t; idx < 2048; idx += 128) {
            int g = idx >> 9, rem = idx & 511;
            int o = rem >> 4, c2 = rem & 15;
            float scale = (g == 0) ? 1.0f : (1.0f / 32.0f);
            float2 w = *(const float2*)(W + o * 256 + g * 32 + c2 * 2);
            w.x *= scale; w.y *= scale;
            uint32_t hi, lo;
            split_pair(w.x, w.y, hi, lo);
            g_Wh4[idx] = hi;
            g_Wl4[idx] = lo;
        }
        return;
    }

    __shared__ float part[128];
    __shared__ float mrow[NC];
    int c = t & 31, q = t >> 5;

    float s = 0.f;
    const float* w;
    float scale;
    float* dst;
    bool addb = false;

    if (gid < 256) {
        int b = gid >> 5, k = gid & 31;
        #pragma unroll
        for (int j = q; j < DD; j += 4) s += g_m1[((b * DD + j) * DD + k) * NC + c];
        w = W + 128; scale = 1.0f / 1024.0f; dst = g_pij + gid * NO;
    } else if (gid < 512) {
        int g = gid - 256;
        int b = g >> 5, j = g & 31;
        #pragma unroll
        for (int k = q; k < DD; k += 4) s += g_m1[((b * DD + j) * DD + k) * NC + c];
        w = W + 160; scale = 1.0f / 1024.0f; dst = g_pik + g * NO;
    } else if (gid < 768) {
        int g = gid - 512;
        int b = g >> 5, i = g & 31;
        #pragma unroll
        for (int k = q; k < DD; k += 4) s += g_m2[((b * DD + i) * DD + k) * NC + c];
        w = W + 192; scale = 1.0f / 1024.0f; dst = g_pjk + g * NO;
    } else {
        int b = gid - 768;
        for (int jk = q; jk < DD * DD; jk += 4) s += g_m1[(b * DD * DD + jk) * NC + c];
        w = W + 224; scale = 1.0f / 32768.0f; dst = g_pall + b * NO; addb = true;
    }
    part[t] = s;
    __syncthreads();
    if (t < 32) mrow[t] = part[t] + part[t + 32] + part[t + 64] + part[t + 96];
    __syncthreads();
    if (t < 32) {
        float acc = 0.f;
        #pragma unroll
        for (int cc = 0; cc < NC; cc++) acc += mrow[cc] * w[t * 256 + cc];
        acc *= scale;
        if (addb) acc += bias[t];
        dst[t] = acc;
    }
}

// ---------------- shared mma tile machinery ----------------
#define XRS 40
#define WRS 40

// stage 128 rows of [row][32f] from src into x_s (stride XRS), coalesced
__device__ __forceinline__ void stage_rows(const float* __restrict__ src, float* x_s, int tid) {
    const float4* xg = (const float4*)src;
    #pragma unroll
    for (int q = 0; q < 8; q++) {
        int idx = q * 128 + tid;
        int row = idx >> 3, c4 = idx & 7;
        *(float4*)(x_s + row * XRS + c4 * 4) = xg[idx];
    }
}

// stage pre-split W group (512 u32 each) into strided smem
__device__ __forceinline__ void stage_wsplit(int group, uint16_t* Wh_s, uint16_t* Wl_s, int tid) {
    const uint32_t* srcH = g_Wh4 + group * 512;
    const uint32_t* srcL = g_Wl4 + group * 512;
    #pragma unroll
    for (int idx = tid; idx < 512; idx += 128) {
        int o = idx >> 4, c2 = idx & 15;
        *(uint32_t*)(Wh_s + o * WRS + c2 * 2) = srcH[idx];
        *(uint32_t*)(Wl_s + o * WRS + c2 * 2) = srcL[idx];
    }
}

// two m16n32 tiles per warp over x_s rows [wid*32, wid*32+32); D back into x_s.
__device__ __forceinline__ void mma_tiles(float* x_s, const uint16_t* Wh_s, const uint16_t* Wl_s,
                                          int wid, int lr, int lc2) {
    #pragma unroll
    for (int t = 0; t < 2; t++) {
        int rbase = wid * 32 + t * 16;
        float D[4][4];
        #pragma unroll
        for (int nc = 0; nc < 4; nc++)
            #pragma unroll
            for (int q = 0; q < 4; q++) D[nc][q] = 0.f;

        #pragma unroll
        for (int kc = 0; kc < 2; kc++) {
            int c = kc * 16 + lc2;
            const float* r0 = x_s + (rbase + lr) * XRS;
            const float* r1 = x_s + (rbase + lr + 8) * XRS;
            float2 f0 = *(const float2*)(r0 + c);
            float2 f1 = *(const float2*)(r1 + c);
            float2 f2 = *(const float2*)(r0 + c + 8);
            float2 f3 = *(const float2*)(r1 + c + 8);
            uint32_t Ah[4], Al[4];
            split_pair(f0.x, f0.y, Ah[0], Al[0]);
            split_pair(f1.x, f1.y, Ah[1], Al[1]);
            split_pair(f2.x, f2.y, Ah[2], Al[2]);
            split_pair(f3.x, f3.y, Ah[3], Al[3]);

            #pragma unroll
            for (int nc = 0; nc < 4; nc++) {
                int off = (nc * 8 + lr) * WRS + kc * 16 + lc2;
                uint32_t bh[2], bl[2];
                bh[0] = *(const uint32_t*)(Wh_s + off);
                bh[1] = *(const uint32_t*)(Wh_s + off + 8);
                bl[0] = *(const uint32_t*)(Wl_s + off);
                bl[1] = *(const uint32_t*)(Wl_s + off + 8);
                MMA16816(D[nc], Ah, bh);
                MMA16816(D[nc], Ah, bl);
                MMA16816(D[nc], Al, bh);
            }
        }

        #pragma unroll
        for (int half = 0; half < 2; half++) {
            int row = rbase + lr + half * 8;
            #pragma unroll
            for (int nc = 0; nc < 4; nc++) {
                *(float2*)(x_s + row * XRS + nc * 8 + lc2) =
                    make_float2(D[nc][half * 2 + 0], D[nc][half * 2 + 1]);
            }
        }
    }
}

// ---------------- K3: PA/PB/PC projections via mma.sync (grid 192 x 128) ----------------
__global__ __launch_bounds__(128) void k_bigproj_mma(void) {
    __shared__ __align__(16) float x_s[128 * XRS];
    __shared__ __align__(4) uint16_t Wh_s[32 * WRS];
    __shared__ __align__(4) uint16_t Wl_s[32 * WRS];

    int tid = threadIdx.x;
    int wid = tid >> 5, lid = tid & 31;
    int lr = lid >> 2, lc2 = (lid & 3) * 2;
    int sel = blockIdx.x >> 6;
    int r0 = (blockIdx.x & 63) * 128;
    const float* src = (sel == 0) ? g_m1 : (sel == 1) ? g_m2 : g_m3;
    float* dstbase = (sel == 0) ? g_PA : (sel == 1) ? g_PB : g_PC;

    stage_wsplit(1 + sel, Wh_s, Wl_s, tid);
    stage_rows(src + (size_t)r0 * 32, x_s, tid);
    __syncthreads();

    mma_tiles(x_s, Wh_s, Wl_s, wid, lr, lc2);
    __syncthreads();

    #pragma unroll
    for (int q = 0; q < 8; q++) {
        int idx = q * 128 + tid;
        int rl = idx >> 3, o4 = idx & 7;
        int p = r0 + rl;
        int b = p >> 10, d1 = (p >> 5) & 31, d2 = p & 31;
        float4 v = *(const float4*)(x_s + rl * XRS + o4 * 4);
        if (sel == 0) {
            float4 a = ((const float4*)(g_pij + (b * 32 + d2) * 32))[o4];
            float4 bq = ((const float4*)(g_pik + (b * 32 + d1) * 32))[o4];
            float4 c = ((const float4*)(g_pall + b * 32))[o4];
            v.x += a.x + bq.x + c.x; v.y += a.y + bq.y + c.y;
            v.z += a.z + bq.z + c.z; v.w += a.w + bq.w + c.w;
        } else if (sel == 1) {
            float4 a = ((const float4*)(g_pjk + (b * 32 + d1) * 32))[o4];
            v.x += a.x; v.y += a.y; v.z += a.z; v.w += a.w;
        }
        ((float4*)(dstbase + (size_t)p * 32))[o4] = v;
    }
}

// ---------------- K4: main projection via mma.sync, phase-free (grid 2048 x 128) ----------------
// A fragments load DIRECTLY from gmem (L2-resident x), issued before the single
// barrier so latency overlaps W staging. D goes to warp-private smem rows
// (stride 40, bank-clean), epilogue is warp-local -> __syncwarp only.
__global__ __launch_bounds__(128) void k_main_mma(const float* __restrict__ x,
                                                  float* __restrict__ out) {
    __shared__ __align__(16) float d_s[128 * XRS];     // D buffer only
    __shared__ __align__(4) uint16_t Wh_s[32 * WRS];
    __shared__ __align__(4) uint16_t Wl_s[32 * WRS];

    int tid = threadIdx.x;
    int wid = tid >> 5, lid = tid & 31;
    int lr = lid >> 2, lc2 = (lid & 3) * 2;
    int p0 = blockIdx.x * 128;

    // ---- issue all 16 A loads up front (independent, L2-resident) ----
    float2 Af[2][2][4];      // [tile][kc][frag]
    #pragma unroll
    for (int t = 0; t < 2; t++) {
        int rbase = wid * 32 + t * 16;
        const float* r0 = x + (size_t)(p0 + rbase + lr) * 32;
        const float* r1 = x + (size_t)(p0 + rbase + lr + 8) * 32;
        #pragma unroll
        for (int kc = 0; kc < 2; kc++) {
            int c = kc * 16 + lc2;
            Af[t][kc][0] = *(const float2*)(r0 + c);
            Af[t][kc][1] = *(const float2*)(r1 + c);
            Af[t][kc][2] = *(const float2*)(r0 + c + 8);
            Af[t][kc][3] = *(const float2*)(r1 + c + 8);
        }
    }

    stage_wsplit(0, Wh_s, Wl_s, tid);
    __syncthreads();          // W_s visible; A loads have been draining meanwhile

    // ---- MMA: two m16 tiles, D into own smem rows ----
    #pragma unroll
    for (int t = 0; t < 2; t++) {
        int rbase = wid * 32 + t * 16;
        float D[4][4];
        #pragma unroll
        for (int nc = 0; nc < 4; nc++)
            #pragma unroll
            for (int q = 0; q < 4; q++) D[nc][q] = 0.f;

        #pragma unroll
        for (int kc = 0; kc < 2; kc++) {
            uint32_t Ah[4], Al[4];
            split_pair(Af[t][kc][0].x, Af[t][kc][0].y, Ah[0], Al[0]);
            split_pair(Af[t][kc][1].x, Af[t][kc][1].y, Ah[1], Al[1]);
            split_pair(Af[t][kc][2].x, Af[t][kc][2].y, Ah[2], Al[2]);
            split_pair(Af[t][kc][3].x, Af[t][kc][3].y, Ah[3], Al[3]);

            #pragma unroll
            for (int nc = 0; nc < 4; nc++) {
                int off = (nc * 8 + lr) * WRS + kc * 16 + lc2;
                uint32_t bh[2], bl[2];
                bh[0] = *(const uint32_t*)(Wh_s + off);
                bh[1] = *(const uint32_t*)(Wh_s + off + 8);
                bl[0] = *(const uint32_t*)(Wl_s + off);
                bl[1] = *(const uint32_t*)(Wl_s + off + 8);
                MMA16816(D[nc], Ah, bh);
                MMA16816(D[nc], Ah, bl);
                MMA16816(D[nc], Al, bh);
            }
        }

        #pragma unroll
        for (int half = 0; half < 2; half++) {
            int row = rbase + lr + half * 8;
            #pragma unroll
            for (int nc = 0; nc < 4; nc++) {
                *(float2*)(d_s + row * XRS + nc * 8 + lc2) =
                    make_float2(D[nc][half * 2 + 0], D[nc][half * 2 + 1]);
            }
        }
    }
    __syncwarp();             // warp-local D visibility; no block barrier

    // ---- warp-local coalesced epilogue: + PA + PB + PC ----
    #pragma unroll
    for (int q = 0; q < 8; q++) {
        int idx = q * 32 + lid;
        int rl = wid * 32 + (idx >> 3), o4 = idx & 7;
        int gr = p0 + rl;
        int k = gr & 31, j = (gr >> 5) & 31, i = (gr >> 10) & 31, b = gr >> 15;
        float4 v = *(const float4*)(d_s + rl * XRS + o4 * 4);
        float4 pa = ((const float4*)(g_PA + (((b * 32 + j) * 32 + k) * 32)))[o4];
        float4 pb = ((const float4*)(g_PB + (((b * 32 + i) * 32 + k) * 32)))[o4];
        float4 pc = ((const float4*)(g_PC + (((b * 32 + i) * 32 + j) * 32)))[o4];
        float4 r;
        r.x = v.x + pa.x + pb.x + pc.x;
        r.y = v.y + pa.y + pb.y + pc.y;
        r.z = v.z + pa.z + pb.z + pc.z;
        r.w = v.w + pa.w + pb.w + pc.w;
        ((float4*)(out + (size_t)gr * 32))[o4] = r;
    }
}

// ---------------- launch ----------------
extern "C" void kernel_launch(void* const* d_in, const int* in_sizes, int n_in,
                              void* d_out, int out_size) {
    const float* x    = (const float*)d_in[0];
    const float* W    = (const float*)d_in[1];
    const float* bias = (const float*)d_in[2];
    float* out = (float*)d_out;

    k_means<<<768, 256>>>(x);
    k_small<<<777, 128>>>(W, bias);
    k_bigproj_mma<<<192, 128>>>();
    k_main_mma<<<2048, 128>>>(x, out);
}

// round 15
// speedup vs baseline: 1.0494x; 1.0494x over previous
#include <cuda_runtime.h>
#include <cuda_bf16.h>
#include <cstdint>

// Problem dims
#define NB 8
#define DD 32
#define NC 32
#define NO 32
// positions = 262144

typedef unsigned long long ull;

// ---------------- scratch ----------------
__device__ float g_m1[NB*DD*DD*NC];
__device__ float g_m2[NB*DD*DD*NC];
__device__ float g_m3[NB*DD*DD*NC];
__device__ float g_pij[NB*DD*NO];
__device__ float g_pik[NB*DD*NO];
__device__ float g_pjk[NB*DD*NO];
__device__ float g_pall[NB*NO];
__device__ float g_PA[NB*DD*DD*NO];
__device__ float g_PB[NB*DD*DD*NO];
__device__ float g_PC[NB*DD*DD*NO];
// pre-split W (bf16 hi/lo pairs, packed 2-per-u32): [group 0..3][o:32][c2:16]
// groups 1..3 pre-scaled by 1/32
__device__ uint32_t g_Wh4[4*512];
__device__ uint32_t g_Wl4[4*512];

// ---------------- helpers ----------------
__device__ __forceinline__ void gdc_wait() {
    asm volatile("griddepcontrol.wait;" ::: "memory");
}
__device__ __forceinline__ void gdc_launch() {
    asm volatile("griddepcontrol.launch_dependents;" ::: "memory");
}

// fp32 pair -> (hi, lo) bf16x2
__device__ __forceinline__ void split_pair(float a, float b, uint32_t& hi, uint32_t& lo) {
    __nv_bfloat162 h = __floats2bfloat162_rn(a, b);
    float2 hf = __bfloat1622float2(h);
    __nv_bfloat162 l = __floats2bfloat162_rn(a - hf.x, b - hf.y);
    hi = *(uint32_t*)&h;
    lo = *(uint32_t*)&l;
}

#define MMA16816(d, a, b) \
    asm volatile("mma.sync.aligned.m16n8k16.row.col.f32.bf16.bf16.f32 " \
                 "{%0,%1,%2,%3}, {%4,%5,%6,%7}, {%8,%9}, {%0,%1,%2,%3};" \
                 : "+f"(d[0]), "+f"(d[1]), "+f"(d[2]), "+f"(d[3]) \
                 : "r"(a[0]), "r"(a[1]), "r"(a[2]), "r"(a[3]), "r"(b[0]), "r"(b[1]))

// ---------------- K1: axis sums, m2+m3 fused into one x pass (grid 512) ----------------
__global__ __launch_bounds__(256) void k_means(const float* __restrict__ x) {
    int t = threadIdx.x;
    const float4* x4 = (const float4*)x;

    if (blockIdx.x < 256) {
        // m1[b][j=d][k][c] = sum_i x[b][i][d][k][c]
        int b = blockIdx.x >> 5, d = blockIdx.x & 31;
        float4 acc = make_float4(0.f, 0.f, 0.f, 0.f);
        #pragma unroll 8
        for (int i = 0; i < DD; i++) {
            float4 v = x4[((b * DD + i) * DD + d) * 256 + t];
            acc.x += v.x; acc.y += v.y; acc.z += v.z; acc.w += v.w;
        }
        ((float4*)g_m1)[(b * DD + d) * 256 + t] = acc;
    } else {
        // fused slab pass over (b, i): m2 (sum over j) then m3 (sum over k);
        // second loop re-reads the same 128KB slab (L1/L2-resident).
        int g = blockIdx.x - 256;
        int b = g >> 5, i = g & 31;
        const float4* slab = x4 + ((size_t)(b * DD + i) * DD) * 256;

        float4 acc2 = make_float4(0.f, 0.f, 0.f, 0.f);
        #pragma unroll 8
        for (int j = 0; j < DD; j++) {
            float4 v = slab[j * 256 + t];
            acc2.x += v.x; acc2.y += v.y; acc2.z += v.z; acc2.w += v.w;
        }
        ((float4*)g_m2)[(b * DD + i) * 256 + t] = acc2;

        int j = t >> 3, c4 = t & 7;
        float4 acc3 = make_float4(0.f, 0.f, 0.f, 0.f);
        #pragma unroll 8
        for (int k = 0; k < DD; k++) {
            float4 v = slab[j * 256 + k * 8 + c4];
            acc3.x += v.x; acc3.y += v.y; acc3.z += v.z; acc3.w += v.w;
        }
        ((float4*)g_m3)[(b * DD + i) * 256 + j * 8 + c4] = acc3;
    }
}

// ---------------- K2: pools + small projections + W split (grid 777, PDL after k_means) ----------------
__global__ __launch_bounds__(128) void k_small(const float* __restrict__ W,
                                               const float* __restrict__ bias) {
    int gid = blockIdx.x;
    int t = threadIdx.x;

    if (gid == 776) {
        // W split precompute: reads only the input W — no dependency wait needed
        #pragma unroll
        for (int idx = t; idx < 2048; idx += 128) {
            int g = idx >> 9, rem = idx & 511;
            int o = rem >> 4, c2 = rem & 15;
            float scale = (g == 0) ? 1.0f : (1.0f / 32.0f);
            float2 w = *(const float2*)(W + o * 256 + g * 32 + c2 * 2);
            w.x *= scale; w.y *= scale;
            uint32_t hi, lo;
            split_pair(w.x, w.y, hi, lo);
            g_Wh4[idx] = hi;
            g_Wl4[idx] = lo;
        }
        gdc_launch();
        return;
    }

    gdc_wait();     // m1/m2 must be complete

    __shared__ float part[128];
    __shared__ float mrow[NC];
    int c = t & 31, q = t >> 5;

    float s = 0.f;
    const float* w;
    float scale;
    float* dst;
    bool addb = false;

    if (gid < 256) {
        int b = gid >> 5, k = gid & 31;
        #pragma unroll
        for (int j = q; j < DD; j += 4) s += g_m1[((b * DD + j) * DD + k) * NC + c];
        w = W + 128; scale = 1.0f / 1024.0f; dst = g_pij + gid * NO;
    } else if (gid < 512) {
        int g = gid - 256;
        int b = g >> 5, j = g & 31;
        #pragma unroll
        for (int k = q; k < DD; k += 4) s += g_m1[((b * DD + j) * DD + k) * NC + c];
        w = W + 160; scale = 1.0f / 1024.0f; dst = g_pik + g * NO;
    } else if (gid < 768) {
        int g = gid - 512;
        int b = g >> 5, i = g & 31;
        #pragma unroll
        for (int k = q; k < DD; k += 4) s += g_m2[((b * DD + i) * DD + k) * NC + c];
        w = W + 192; scale = 1.0f / 1024.0f; dst = g_pjk + g * NO;
    } else {
        int b = gid - 768;
        for (int jk = q; jk < DD * DD; jk += 4) s += g_m1[(b * DD * DD + jk) * NC + c];
        w = W + 224; scale = 1.0f / 32768.0f; dst = g_pall + b * NO; addb = true;
    }
    part[t] = s;
    __syncthreads();
    if (t < 32) mrow[t] = part[t] + part[t + 32] + part[t + 64] + part[t + 96];
    __syncthreads();
    if (t < 32) {
        float acc = 0.f;
        #pragma unroll
        for (int cc = 0; cc < NC; cc++) acc += mrow[cc] * w[t * 256 + cc];
        acc *= scale;
        if (addb) acc += bias[t];
        dst[t] = acc;
    }
    gdc_launch();
}

// ---------------- shared mma tile machinery ----------------
#define XRS 40
#define WRS 40

__device__ __forceinline__ void stage_rows(const float* __restrict__ src, float* x_s, int tid) {
    const float4* xg = (const float4*)src;
    #pragma unroll
    for (int q = 0; q < 8; q++) {
        int idx = q * 128 + tid;
        int row = idx >> 3, c4 = idx & 7;
        *(float4*)(x_s + row * XRS + c4 * 4) = xg[idx];
    }
}

__device__ __forceinline__ void stage_wsplit(int group, uint16_t* Wh_s, uint16_t* Wl_s, int tid) {
    const uint32_t* srcH = g_Wh4 + group * 512;
    const uint32_t* srcL = g_Wl4 + group * 512;
    #pragma unroll
    for (int idx = tid; idx < 512; idx += 128) {
        int o = idx >> 4, c2 = idx & 15;
        *(uint32_t*)(Wh_s + o * WRS + c2 * 2) = srcH[idx];
        *(uint32_t*)(Wl_s + o * WRS + c2 * 2) = srcL[idx];
    }
}

// two m16n32 tiles per warp over x_s rows [wid*32, wid*32+32); D back into x_s.
__device__ __forceinline__ void mma_tiles(float* x_s, const uint16_t* Wh_s, const uint16_t* Wl_s,
                                          int wid, int lr, int lc2) {
    #pragma unroll
    for (int t = 0; t < 2; t++) {
        int rbase = wid * 32 + t * 16;
        float D[4][4];
        #pragma unroll
        for (int nc = 0; nc < 4; nc++)
            #pragma unroll
            for (int q = 0; q < 4; q++) D[nc][q] = 0.f;

        #pragma unroll
        for (int kc = 0; kc < 2; kc++) {
            int c = kc * 16 + lc2;
            const float* r0 = x_s + (rbase + lr) * XRS;
            const float* r1 = x_s + (rbase + lr + 8) * XRS;
            float2 f0 = *(const float2*)(r0 + c);
            float2 f1 = *(const float2*)(r1 + c);
            float2 f2 = *(const float2*)(r0 + c + 8);
            float2 f3 = *(const float2*)(r1 + c + 8);
            uint32_t Ah[4], Al[4];
            split_pair(f0.x, f0.y, Ah[0], Al[0]);
            split_pair(f1.x, f1.y, Ah[1], Al[1]);
            split_pair(f2.x, f2.y, Ah[2], Al[2]);
            split_pair(f3.x, f3.y, Ah[3], Al[3]);

            #pragma unroll
            for (int nc = 0; nc < 4; nc++) {
                int off = (nc * 8 + lr) * WRS + kc * 16 + lc2;
                uint32_t bh[2], bl[2];
                bh[0] = *(const uint32_t*)(Wh_s + off);
                bh[1] = *(const uint32_t*)(Wh_s + off + 8);
                bl[0] = *(const uint32_t*)(Wl_s + off);
                bl[1] = *(const uint32_t*)(Wl_s + off + 8);
                MMA16816(D[nc], Ah, bh);
                MMA16816(D[nc], Ah, bl);
                MMA16816(D[nc], Al, bh);
            }
        }

        #pragma unroll
        for (int half = 0; half < 2; half++) {
            int row = rbase + lr + half * 8;
            #pragma unroll
            for (int nc = 0; nc < 4; nc++) {
                *(float2*)(x_s + row * XRS + nc * 8 + lc2) =
                    make_float2(D[nc][half * 2 + 0], D[nc][half * 2 + 1]);
            }
        }
    }
}

// ---------------- K3: PA/PB/PC projections via mma.sync (grid 192, PDL after k_small) ----------------
// Preamble (stage_rows from m1/m2/m3) runs BEFORE the dependency wait:
// k_bigproj can only launch once every k_small block completed, and k_small
// blocks complete only after their own wait on k_means — so m1/m2/m3 are done.
__global__ __launch_bounds__(128) void k_bigproj_mma(void) {
    __shared__ __align__(16) float x_s[128 * XRS];
    __shared__ __align__(4) uint16_t Wh_s[32 * WRS];
    __shared__ __align__(4) uint16_t Wl_s[32 * WRS];

    int tid = threadIdx.x;
    int wid = tid >> 5, lid = tid & 31;
    int lr = lid >> 2, lc2 = (lid & 3) * 2;
    int sel = blockIdx.x >> 6;
    int r0 = (blockIdx.x & 63) * 128;
    const float* src = (sel == 0) ? g_m1 : (sel == 1) ? g_m2 : g_m3;
    float* dstbase = (sel == 0) ? g_PA : (sel == 1) ? g_PB : g_PC;

    stage_rows(src + (size_t)r0 * 32, x_s, tid);   // safe pre-wait (see above)
    gdc_wait();                                     // g_Wh4/g_Wl4 + pools ready
    stage_wsplit(1 + sel, Wh_s, Wl_s, tid);
    __syncthreads();

    mma_tiles(x_s, Wh_s, Wl_s, wid, lr, lc2);
    __syncthreads();

    #pragma unroll
    for (int q = 0; q < 8; q++) {
        int idx = q * 128 + tid;
        int rl = idx >> 3, o4 = idx & 7;
        int p = r0 + rl;
        int b = p >> 10, d1 = (p >> 5) & 31, d2 = p & 31;
        float4 v = *(const float4*)(x_s + rl * XRS + o4 * 4);
        if (sel == 0) {
            float4 a = ((const float4*)(g_pij + (b * 32 + d2) * 32))[o4];
            float4 bq = ((const float4*)(g_pik + (b * 32 + d1) * 32))[o4];
            float4 c = ((const float4*)(g_pall + b * 32))[o4];
            v.x += a.x + bq.x + c.x; v.y += a.y + bq.y + c.y;
            v.z += a.z + bq.z + c.z; v.w += a.w + bq.w + c.w;
        } else if (sel == 1) {
            float4 a = ((const float4*)(g_pjk + (b * 32 + d1) * 32))[o4];
            v.x += a.x; v.y += a.y; v.z += a.z; v.w += a.w;
        }
        ((float4*)(dstbase + (size_t)p * 32))[o4] = v;
    }
    gdc_launch();
}

// ---------------- K4: main projection via mma.sync (grid 2048, PDL after k_bigproj) ----------------
// A fragments (x only — dependence-free) are issued BEFORE the wait, so their
// latency overlaps the tail of k_bigproj. Everything touching g_W*/g_P* comes after.
__global__ __launch_bounds__(128) void k_main_mma(const float* __restrict__ x,
                                                  float* __restrict__ out) {
    __shared__ __align__(16) float d_s[128 * XRS];
    __shared__ __align__(4) uint16_t Wh_s[32 * WRS];
    __shared__ __align__(4) uint16_t Wl_s[32 * WRS];

    int tid = threadIdx.x;
    int wid = tid >> 5, lid = tid & 31;
    int lr = lid >> 2, lc2 = (lid & 3) * 2;
    int p0 = blockIdx.x * 128;

    // ---- A loads up front (x is an input: no dependency) ----
    float2 Af[2][2][4];
    #pragma unroll
    for (int t = 0; t < 2; t++) {
        int rbase = wid * 32 + t * 16;
        const float* r0 = x + (size_t)(p0 + rbase + lr) * 32;
        const float* r1 = x + (size_t)(p0 + rbase + lr + 8) * 32;
        #pragma unroll
        for (int kc = 0; kc < 2; kc++) {
            int c = kc * 16 + lc2;
            Af[t][kc][0] = *(const float2*)(r0 + c);
            Af[t][kc][1] = *(const float2*)(r1 + c);
            Af[t][kc][2] = *(const float2*)(r0 + c + 8);
            Af[t][kc][3] = *(const float2*)(r1 + c + 8);
        }
    }

    gdc_wait();               // W split + PA/PB/PC ready
    stage_wsplit(0, Wh_s, Wl_s, tid);
    __syncthreads();

    #pragma unroll
    for (int t = 0; t < 2; t++) {
        int rbase = wid * 32 + t * 16;
        float D[4][4];
        #pragma unroll
        for (int nc = 0; nc < 4; nc++)
            #pragma unroll
            for (int q = 0; q < 4; q++) D[nc][q] = 0.f;

        #pragma unroll
        for (int kc = 0; kc < 2; kc++) {
            uint32_t Ah[4], Al[4];
            split_pair(Af[t][kc][0].x, Af[t][kc][0].y, Ah[0], Al[0]);
            split_pair(Af[t][kc][1].x, Af[t][kc][1].y, Ah[1], Al[1]);
            split_pair(Af[t][kc][2].x, Af[t][kc][2].y, Ah[2], Al[2]);
            split_pair(Af[t][kc][3].x, Af[t][kc][3].y, Ah[3], Al[3]);

            #pragma unroll
            for (int nc = 0; nc < 4; nc++) {
                int off = (nc * 8 + lr) * WRS + kc * 16 + lc2;
                uint32_t bh[2], bl[2];
                bh[0] = *(const uint32_t*)(Wh_s + off);
                bh[1] = *(const uint32_t*)(Wh_s + off + 8);
                bl[0] = *(const uint32_t*)(Wl_s + off);
                bl[1] = *(const uint32_t*)(Wl_s + off + 8);
                MMA16816(D[nc], Ah, bh);
                MMA16816(D[nc], Ah, bl);
                MMA16816(D[nc], Al, bh);
            }
        }

        #pragma unroll
        for (int half = 0; half < 2; half++) {
            int row = rbase + lr + half * 8;
            #pragma unroll
            for (int nc = 0; nc < 4; nc++) {
                *(float2*)(d_s + row * XRS + nc * 8 + lc2) =
                    make_float2(D[nc][half * 2 + 0], D[nc][half * 2 + 1]);
            }
        }
    }
    __syncwarp();

    #pragma unroll
    for (int q = 0; q < 8; q++) {
        int idx = q * 32 + lid;
        int rl = wid * 32 + (idx >> 3), o4 = idx & 7;
        int gr = p0 + rl;
        int k = gr & 31, j = (gr >> 5) & 31, i = (gr >> 10) & 31, b = gr >> 15;
        float4 v = *(const float4*)(d_s + rl * XRS + o4 * 4);
        float4 pa = ((const float4*)(g_PA + (((b * 32 + j) * 32 + k) * 32)))[o4];
        float4 pb = ((const float4*)(g_PB + (((b * 32 + i) * 32 + k) * 32)))[o4];
        float4 pc = ((const float4*)(g_PC + (((b * 32 + i) * 32 + j) * 32)))[o4];
        float4 r;
        r.x = v.x + pa.x + pb.x + pc.x;
        r.y = v.y + pa.y + pb.y + pc.y;
        r.z = v.z + pa.z + pb.z + pc.z;
        r.w = v.w + pa.w + pb.w + pc.w;
        ((float4*)(out + (size_t)gr * 32))[o4] = r;
    }
}

// ---------------- launch ----------------
extern "C" void kernel_launch(void* const* d_in, const int* in_sizes, int n_in,
                              void* d_out, int out_size) {
    const float* x    = (const float*)d_in[0];
    const float* W    = (const float*)d_in[1];
    const float* bias = (const float*)d_in[2];
    float* out = (float*)d_out;

    k_means<<<512, 256>>>(x);

    cudaLaunchAttribute at[1];
    at[0].id = cudaLaunchAttributeProgrammaticStreamSerialization;
    at[0].val.programmaticStreamSerializationAllowed = 1;

    {
        cudaLaunchConfig_t cfg = {};
        cfg.gridDim = dim3(777, 1, 1);
        cfg.blockDim = dim3(128, 1, 1);
        cfg.attrs = at; cfg.numAttrs = 1;
        cudaLaunchKernelEx(&cfg, k_small, W, bias);
    }
    {
        cudaLaunchConfig_t cfg = {};
        cfg.gridDim = dim3(192, 1, 1);
        cfg.blockDim = dim3(128, 1, 1);
        cfg.attrs = at; cfg.numAttrs = 1;
        cudaLaunchKernelEx(&cfg, k_bigproj_mma);
    }
    {
        cudaLaunchConfig_t cfg = {};
        cfg.gridDim = dim3(2048, 1, 1);
        cfg.blockDim = dim3(128, 1, 1);
        cfg.attrs = at; cfg.numAttrs = 1;
        cudaLaunchKernelEx(&cfg, k_main_mma, x, out);
    }
}

// round 16
// speedup vs baseline: 1.1012x; 1.0494x over previous
#include <cuda_runtime.h>
#include <cuda_fp16.h>
#include <cstdint>

// Problem dims
#define NB 8
#define DD 32
#define NC 32
#define NO 32
// positions = 262144

typedef unsigned long long ull;

// ---------------- scratch ----------------
__device__ float g_m1[NB*DD*DD*NC];
__device__ float g_m2[NB*DD*DD*NC];
__device__ float g_m3[NB*DD*DD*NC];
__device__ float g_pij[NB*DD*NO];
__device__ float g_pik[NB*DD*NO];
__device__ float g_pjk[NB*DD*NO];
__device__ float g_pall[NB*NO];
__device__ float g_PA[NB*DD*DD*NO];
__device__ float g_PB[NB*DD*DD*NO];
__device__ float g_PC[NB*DD*DD*NO];
// pre-split W (fp16 hi/lo pairs, packed half2-per-u32): [group 0..3][o:32][c2:16]
// groups 1..3 pre-scaled by 1/32
__device__ uint32_t g_Wh4[4*512];
__device__ uint32_t g_Wl4[4*512];

// ---------------- helpers ----------------
__device__ __forceinline__ void gdc_wait() {
    asm volatile("griddepcontrol.wait;" ::: "memory");
}
__device__ __forceinline__ void gdc_launch() {
    asm volatile("griddepcontrol.launch_dependents;" ::: "memory");
}

// fp32 pair -> packed fp16x2 (single cvt)
__device__ __forceinline__ uint32_t f16pack(float a, float b) {
    __half2 h = __floats2half2_rn(a, b);
    return *(uint32_t*)&h;
}
// fp32 pair -> (hi, lo) fp16x2 split (W precompute only)
__device__ __forceinline__ void split_pair_f16(float a, float b, uint32_t& hi, uint32_t& lo) {
    __half2 h = __floats2half2_rn(a, b);
    float2 hf = __half22float2(h);
    __half2 l = __floats2half2_rn(a - hf.x, b - hf.y);
    hi = *(uint32_t*)&h;
    lo = *(uint32_t*)&l;
}

#define MMAF16(d, a, b) \
    asm volatile("mma.sync.aligned.m16n8k16.row.col.f32.f16.f16.f32 " \
                 "{%0,%1,%2,%3}, {%4,%5,%6,%7}, {%8,%9}, {%0,%1,%2,%3};" \
                 : "+f"(d[0]), "+f"(d[1]), "+f"(d[2]), "+f"(d[3]) \
                 : "r"(a[0]), "r"(a[1]), "r"(a[2]), "r"(a[3]), "r"(b[0]), "r"(b[1]))

// ---------------- K1: axis sums, m2+m3 fused into one x pass (grid 512) ----------------
__global__ __launch_bounds__(256) void k_means(const float* __restrict__ x) {
    int t = threadIdx.x;
    const float4* x4 = (const float4*)x;

    if (blockIdx.x < 256) {
        int b = blockIdx.x >> 5, d = blockIdx.x & 31;
        float4 acc = make_float4(0.f, 0.f, 0.f, 0.f);
        #pragma unroll 8
        for (int i = 0; i < DD; i++) {
            float4 v = x4[((b * DD + i) * DD + d) * 256 + t];
            acc.x += v.x; acc.y += v.y; acc.z += v.z; acc.w += v.w;
        }
        ((float4*)g_m1)[(b * DD + d) * 256 + t] = acc;
    } else {
        int g = blockIdx.x - 256;
        int b = g >> 5, i = g & 31;
        const float4* slab = x4 + ((size_t)(b * DD + i) * DD) * 256;

        float4 acc2 = make_float4(0.f, 0.f, 0.f, 0.f);
        #pragma unroll 8
        for (int j = 0; j < DD; j++) {
            float4 v = slab[j * 256 + t];
            acc2.x += v.x; acc2.y += v.y; acc2.z += v.z; acc2.w += v.w;
        }
        ((float4*)g_m2)[(b * DD + i) * 256 + t] = acc2;

        int j = t >> 3, c4 = t & 7;
        float4 acc3 = make_float4(0.f, 0.f, 0.f, 0.f);
        #pragma unroll 8
        for (int k = 0; k < DD; k++) {
            float4 v = slab[j * 256 + k * 8 + c4];
            acc3.x += v.x; acc3.y += v.y; acc3.z += v.z; acc3.w += v.w;
        }
        ((float4*)g_m3)[(b * DD + i) * 256 + j * 8 + c4] = acc3;
    }
}

// ---------------- K2: pools + small projections + W split (grid 777, PDL) ----------------
__global__ __launch_bounds__(128) void k_small(const float* __restrict__ W,
                                               const float* __restrict__ bias) {
    int gid = blockIdx.x;
    int t = threadIdx.x;

    if (gid == 776) {
        #pragma unroll
        for (int idx = t; idx < 2048; idx += 128) {
            int g = idx >> 9, rem = idx & 511;
            int o = rem >> 4, c2 = rem & 15;
            float scale = (g == 0) ? 1.0f : (1.0f / 32.0f);
            float2 w = *(const float2*)(W + o * 256 + g * 32 + c2 * 2);
            w.x *= scale; w.y *= scale;
            uint32_t hi, lo;
            split_pair_f16(w.x, w.y, hi, lo);
            g_Wh4[idx] = hi;
            g_Wl4[idx] = lo;
        }
        gdc_launch();
        return;
    }

    gdc_wait();

    __shared__ float part[128];
    __shared__ float mrow[NC];
    int c = t & 31, q = t >> 5;

    float s = 0.f;
    const float* w;
    float scale;
    float* dst;
    bool addb = false;

    if (gid < 256) {
        int b = gid >> 5, k = gid & 31;
        #pragma unroll
        for (int j = q; j < DD; j += 4) s += g_m1[((b * DD + j) * DD + k) * NC + c];
        w = W + 128; scale = 1.0f / 1024.0f; dst = g_pij + gid * NO;
    } else if (gid < 512) {
        int g = gid - 256;
        int b = g >> 5, j = g & 31;
        #pragma unroll
        for (int k = q; k < DD; k += 4) s += g_m1[((b * DD + j) * DD + k) * NC + c];
        w = W + 160; scale = 1.0f / 1024.0f; dst = g_pik + g * NO;
    } else if (gid < 768) {
        int g = gid - 512;
        int b = g >> 5, i = g & 31;
        #pragma unroll
        for (int k = q; k < DD; k += 4) s += g_m2[((b * DD + i) * DD + k) * NC + c];
        w = W + 192; scale = 1.0f / 1024.0f; dst = g_pjk + g * NO;
    } else {
        int b = gid - 768;
        for (int jk = q; jk < DD * DD; jk += 4) s += g_m1[(b * DD * DD + jk) * NC + c];
        w = W + 224; scale = 1.0f / 32768.0f; dst = g_pall + b * NO; addb = true;
    }
    part[t] = s;
    __syncthreads();
    if (t < 32) mrow[t] = part[t] + part[t + 32] + part[t + 64] + part[t + 96];
    __syncthreads();
    if (t < 32) {
        float acc = 0.f;
        #pragma unroll
        for (int cc = 0; cc < NC; cc++) acc += mrow[cc] * w[t * 256 + cc];
        acc *= scale;
        if (addb) acc += bias[t];
        dst[t] = acc;
    }
    gdc_launch();
}

// ---------------- shared mma tile machinery ----------------
#define XRS 40
#define WRS 40

__device__ __forceinline__ void stage_rows(const float* __restrict__ src, float* x_s, int tid) {
    const float4* xg = (const float4*)src;
    #pragma unroll
    for (int q = 0; q < 8; q++) {
        int idx = q * 128 + tid;
        int row = idx >> 3, c4 = idx & 7;
        *(float4*)(x_s + row * XRS + c4 * 4) = xg[idx];
    }
}

__device__ __forceinline__ void stage_wsplit(int group, uint16_t* Wh_s, uint16_t* Wl_s, int tid) {
    const uint32_t* srcH = g_Wh4 + group * 512;
    const uint32_t* srcL = g_Wl4 + group * 512;
    #pragma unroll
    for (int idx = tid; idx < 512; idx += 128) {
        int o = idx >> 4, c2 = idx & 15;
        *(uint32_t*)(Wh_s + o * WRS + c2 * 2) = srcH[idx];
        *(uint32_t*)(Wl_s + o * WRS + c2 * 2) = srcL[idx];
    }
}

// two m16n32 tiles per warp over x_s rows [wid*32, wid*32+32); D back into x_s.
// fp16 2-term: D = Ah*Bh + Ah*Bl (A truncation err ~2^-12, inside tolerance).
__device__ __forceinline__ void mma_tiles(float* x_s, const uint16_t* Wh_s, const uint16_t* Wl_s,
                                          int wid, int lr, int lc2) {
    #pragma unroll
    for (int t = 0; t < 2; t++) {
        int rbase = wid * 32 + t * 16;
        float D[4][4];
        #pragma unroll
        for (int nc = 0; nc < 4; nc++)
            #pragma unroll
            for (int q = 0; q < 4; q++) D[nc][q] = 0.f;

        #pragma unroll
        for (int kc = 0; kc < 2; kc++) {
            int c = kc * 16 + lc2;
            const float* r0 = x_s + (rbase + lr) * XRS;
            const float* r1 = x_s + (rbase + lr + 8) * XRS;
            float2 f0 = *(const float2*)(r0 + c);
            float2 f1 = *(const float2*)(r1 + c);
            float2 f2 = *(const float2*)(r0 + c + 8);
            float2 f3 = *(const float2*)(r1 + c + 8);
            uint32_t Ah[4];
            Ah[0] = f16pack(f0.x, f0.y);
            Ah[1] = f16pack(f1.x, f1.y);
            Ah[2] = f16pack(f2.x, f2.y);
            Ah[3] = f16pack(f3.x, f3.y);

            #pragma unroll
            for (int nc = 0; nc < 4; nc++) {
                int off = (nc * 8 + lr) * WRS + kc * 16 + lc2;
                uint32_t bh[2], bl[2];
                bh[0] = *(const uint32_t*)(Wh_s + off);
                bh[1] = *(const uint32_t*)(Wh_s + off + 8);
                bl[0] = *(const uint32_t*)(Wl_s + off);
                bl[1] = *(const uint32_t*)(Wl_s + off + 8);
                MMAF16(D[nc], Ah, bh);
                MMAF16(D[nc], Ah, bl);
            }
        }

        #pragma unroll
        for (int half = 0; half < 2; half++) {
            int row = rbase + lr + half * 8;
            #pragma unroll
            for (int nc = 0; nc < 4; nc++) {
                *(float2*)(x_s + row * XRS + nc * 8 + lc2) =
                    make_float2(D[nc][half * 2 + 0], D[nc][half * 2 + 1]);
            }
        }
    }
}

// ---------------- K3: PA/PB/PC projections via mma.sync (grid 192, PDL) ----------------
__global__ __launch_bounds__(128) void k_bigproj_mma(void) {
    __shared__ __align__(16) float x_s[128 * XRS];
    __shared__ __align__(4) uint16_t Wh_s[32 * WRS];
    __shared__ __align__(4) uint16_t Wl_s[32 * WRS];

    int tid = threadIdx.x;
    int wid = tid >> 5, lid = tid & 31;
    int lr = lid >> 2, lc2 = (lid & 3) * 2;
    int sel = blockIdx.x >> 6;
    int r0 = (blockIdx.x & 63) * 128;
    const float* src = (sel == 0) ? g_m1 : (sel == 1) ? g_m2 : g_m3;
    float* dstbase = (sel == 0) ? g_PA : (sel == 1) ? g_PB : g_PC;

    stage_rows(src + (size_t)r0 * 32, x_s, tid);   // safe pre-wait (transitive dep)
    gdc_wait();
    stage_wsplit(1 + sel, Wh_s, Wl_s, tid);
    __syncthreads();

    mma_tiles(x_s, Wh_s, Wl_s, wid, lr, lc2);
    __syncthreads();

    // block-constant pool bases: p = r0 + rl, b fixed, d1 = d10 + (rl>>5), d2 = rl&31
    int b = r0 >> 10, d10 = (r0 >> 5) & 31;
    const float* pijb = g_pij + b * 1024;                // + (rl&31)*32
    const float* pikb = g_pik + (b * 32 + d10) * 32;     // + (rl>>5)*32
    const float* pjkb = g_pjk + (b * 32 + d10) * 32;     // + (rl>>5)*32
    const float* pallb = g_pall + b * 32;
    float* dstb = dstbase + (size_t)r0 * 32;             // + rl*32

    #pragma unroll
    for (int q = 0; q < 8; q++) {
        int idx = q * 128 + tid;
        int rl = idx >> 3, o4 = idx & 7;
        float4 v = *(const float4*)(x_s + rl * XRS + o4 * 4);
        if (sel == 0) {
            float4 a = ((const float4*)(pijb + (rl & 31) * 32))[o4];
            float4 bq = ((const float4*)(pikb + (rl >> 5) * 32))[o4];
            float4 c = ((const float4*)pallb)[o4];
            v.x += a.x + bq.x + c.x; v.y += a.y + bq.y + c.y;
            v.z += a.z + bq.z + c.z; v.w += a.w + bq.w + c.w;
        } else if (sel == 1) {
            float4 a = ((const float4*)(pjkb + (rl >> 5) * 32))[o4];
            v.x += a.x; v.y += a.y; v.z += a.z; v.w += a.w;
        }
        ((float4*)(dstb + rl * 32))[o4] = v;
    }
    gdc_launch();
}

// ---------------- K4: main projection via mma.sync fp16 (grid 2048, PDL) ----------------
__global__ __launch_bounds__(128) void k_main_mma(const float* __restrict__ x,
                                                  float* __restrict__ out) {
    __shared__ __align__(16) float d_s[128 * XRS];
    __shared__ __align__(4) uint16_t Wh_s[32 * WRS];
    __shared__ __align__(4) uint16_t Wl_s[32 * WRS];

    int tid = threadIdx.x;
    int wid = tid >> 5, lid = tid & 31;
    int lr = lid >> 2, lc2 = (lid & 3) * 2;
    int p0 = blockIdx.x * 128;

    // ---- A loads up front (x is an input: no dependency) ----
    float2 Af[2][2][4];
    #pragma unroll
    for (int t = 0; t < 2; t++) {
        int rbase = wid * 32 + t * 16;
        const float* r0 = x + (size_t)(p0 + rbase + lr) * 32;
        const float* r1 = x + (size_t)(p0 + rbase + lr + 8) * 32;
        #pragma unroll
        for (int kc = 0; kc < 2; kc++) {
            int c = kc * 16 + lc2;
            Af[t][kc][0] = *(const float2*)(r0 + c);
            Af[t][kc][1] = *(const float2*)(r1 + c);
            Af[t][kc][2] = *(const float2*)(r0 + c + 8);
            Af[t][kc][3] = *(const float2*)(r1 + c + 8);
        }
    }

    gdc_wait();
    stage_wsplit(0, Wh_s, Wl_s, tid);
    __syncthreads();

    #pragma unroll
    for (int t = 0; t < 2; t++) {
        int rbase = wid * 32 + t * 16;
        float D[4][4];
        #pragma unroll
        for (int nc = 0; nc < 4; nc++)
            #pragma unroll
            for (int q = 0; q < 4; q++) D[nc][q] = 0.f;

        #pragma unroll
        for (int kc = 0; kc < 2; kc++) {
            uint32_t Ah[4];
            Ah[0] = f16pack(Af[t][kc][0].x, Af[t][kc][0].y);
            Ah[1] = f16pack(Af[t][kc][1].x, Af[t][kc][1].y);
            Ah[2] = f16pack(Af[t][kc][2].x, Af[t][kc][2].y);
            Ah[3] = f16pack(Af[t][kc][3].x, Af[t][kc][3].y);

            #pragma unroll
            for (int nc = 0; nc < 4; nc++) {
                int off = (nc * 8 + lr) * WRS + kc * 16 + lc2;
                uint32_t bh[2], bl[2];
                bh[0] = *(const uint32_t*)(Wh_s + off);
                bh[1] = *(const uint32_t*)(Wh_s + off + 8);
                bl[0] = *(const uint32_t*)(Wl_s + off);
                bl[1] = *(const uint32_t*)(Wl_s + off + 8);
                MMAF16(D[nc], Ah, bh);
                MMAF16(D[nc], Ah, bl);
            }
        }

        #pragma unroll
        for (int half = 0; half < 2; half++) {
            int row = rbase + lr + half * 8;
            #pragma unroll
            for (int nc = 0; nc < 4; nc++) {
                *(float2*)(d_s + row * XRS + nc * 8 + lc2) =
                    make_float2(D[nc][half * 2 + 0], D[nc][half * 2 + 1]);
            }
        }
    }
    __syncwarp();

    // block-constant epilogue bases: b,i fixed; j = j0 + (rl>>5), k = rl&31
    int b = p0 >> 15, i = (p0 >> 10) & 31, j0 = (p0 >> 5) & 31;
    const float* PAb = g_PA + ((size_t)(b * 32 + j0) * 32) * 32;   // + rl*32
    const float* PBb = g_PB + ((size_t)(b * 32 + i) * 32) * 32;    // + (rl&31)*32
    const float* PCb = g_PC + ((size_t)(b * 32 + i) * 32 + j0) * 32; // + (rl>>5)*32
    float* outb = out + (size_t)p0 * 32;                            // + rl*32

    #pragma unroll
    for (int q = 0; q < 8; q++) {
        int idx = q * 32 + lid;
        int rl = wid * 32 + (idx >> 3), o4 = idx & 7;
        float4 v = *(const float4*)(d_s + rl * XRS + o4 * 4);
        float4 pa = ((const float4*)(PAb + rl * 32))[o4];
        float4 pb = ((const float4*)(PBb + (rl & 31) * 32))[o4];
        float4 pc = ((const float4*)(PCb + (rl >> 5) * 32))[o4];
        float4 r;
        r.x = v.x + pa.x + pb.x + pc.x;
        r.y = v.y + pa.y + pb.y + pc.y;
        r.z = v.z + pa.z + pb.z + pc.z;
        r.w = v.w + pa.w + pb.w + pc.w;
        ((float4*)(outb + rl * 32))[o4] = r;
    }
}

// ---------------- launch ----------------
extern "C" void kernel_launch(void* const* d_in, const int* in_sizes, int n_in,
                              void* d_out, int out_size) {
    const float* x    = (const float*)d_in[0];
    const float* W    = (const float*)d_in[1];
    const float* bias = (const float*)d_in[2];
    float* out = (float*)d_out;

    k_means<<<512, 256>>>(x);

    cudaLaunchAttribute at[1];
    at[0].id = cudaLaunchAttributeProgrammaticStreamSerialization;
    at[0].val.programmaticStreamSerializationAllowed = 1;

    {
        cudaLaunchConfig_t cfg = {};
        cfg.gridDim = dim3(777, 1, 1);
        cfg.blockDim = dim3(128, 1, 1);
        cfg.attrs = at; cfg.numAttrs = 1;
        cudaLaunchKernelEx(&cfg, k_small, W, bias);
    }
    {
        cudaLaunchConfig_t cfg = {};
        cfg.gridDim = dim3(192, 1, 1);
        cfg.blockDim = dim3(128, 1, 1);
        cfg.attrs = at; cfg.numAttrs = 1;
        cudaLaunchKernelEx(&cfg, k_bigproj_mma);
    }
    {
        cudaLaunchConfig_t cfg = {};
        cfg.gridDim = dim3(2048, 1, 1);
        cfg.blockDim = dim3(128, 1, 1);
        cfg.attrs = at; cfg.numAttrs = 1;
        cudaLaunchKernelEx(&cfg, k_main_mma, x, out);
    }
}